// round 15
// baseline (speedup 1.0000x reference)
#include <cuda_runtime.h>
#include <math.h>

#define GD 64
#define SD 32
#define NV (GD*GD*GD)
#define NP (SD*SD*SD)

// ---------------- device scratch ----------------
__device__ float g_prob[NV*16];            // PAR-MAJOR: addr = ((par<<15)|parentLin)*16
__device__ float g_hs[8][NV*16];
__device__ float g_h1[NP*16];
__device__ unsigned char g_occx[NV];
__device__ unsigned char g_pocc[NP];
__device__ unsigned char g_minp[NV];
__device__ unsigned char g_moutp[NV];

struct K1 {
    const float* w[8]; const float* b[8];
    const float* w20; const float* b20;
    int n_ent;
    unsigned cand[26]; unsigned char es[26]; unsigned char par[26];
};
struct K2 {
    const float* w[8]; const float* b[8];
    int n_ent;
    unsigned cand[9]; unsigned char es[9]; unsigned char par[9];
};

// ---------------- packed f32x2 helpers ----------------
__device__ __forceinline__ unsigned long long pk2(float lo, float hi) {
    unsigned long long r;
    asm("mov.b64 %0, {%1, %2};" : "=l"(r) : "f"(lo), "f"(hi));
    return r;
}
__device__ __forceinline__ unsigned long long pk2(float v) { return pk2(v, v); }
__device__ __forceinline__ void upk2(unsigned long long v, float& lo, float& hi) {
    asm("mov.b64 {%0, %1}, %2;" : "=f"(lo), "=f"(hi) : "l"(v));
}
__device__ __forceinline__ void f2fma(unsigned long long& d, unsigned long long a, unsigned long long b) {
    asm("fma.rn.f32x2 %0, %1, %2, %0;" : "+l"(d) : "l"(a), "l"(b));
}
__device__ __forceinline__ void gemv16_f2(unsigned long long* A, const float* in,
                                          const float* wrow) {
    const ulonglong2* wp = (const ulonglong2*)wrow;
    #pragma unroll
    for (int cin=0; cin<16; cin++) {
        unsigned long long v2 = pk2(in[cin]);
        ulonglong2 w01 = wp[cin*4+0];
        ulonglong2 w23 = wp[cin*4+1];
        ulonglong2 w45 = wp[cin*4+2];
        ulonglong2 w67 = wp[cin*4+3];
        f2fma(A[0], v2, w01.x); f2fma(A[1], v2, w01.y);
        f2fma(A[2], v2, w23.x); f2fma(A[3], v2, w23.y);
        f2fma(A[4], v2, w45.x); f2fma(A[5], v2, w45.y);
        f2fma(A[6], v2, w67.x); f2fma(A[7], v2, w67.y);
    }
}

// ---------------- init: occ + pocc ----------------
__global__ void k_init(const float* __restrict__ x) {
    int p = blockIdx.x*256 + threadIdx.x;
    if (p >= NP) return;
    int px = p>>10, py = (p>>5)&31, pz = p&31;
    int bx = px<<1, by = py<<1, bz = pz<<1;
    unsigned char o = 0;
    #pragma unroll
    for (int a=0;a<2;a++)
    #pragma unroll
    for (int b=0;b<2;b++)
    #pragma unroll
    for (int c=0;c<2;c++) {
        int v = ((bx+a)<<12)|((by+b)<<6)|(bz+c);
        unsigned char oc = (x[v] > 0.f) ? 1 : 0;
        g_occx[v] = oc;
        o |= oc;
    }
    g_pocc[p] = o;
}

// ---------------- fused: masks (par-major) + labels + FEL conv1 ----------------
__global__ void k_maskfel1(float* __restrict__ out,
                           const float* __restrict__ wf1, const float* __restrict__ bf1) {
    __shared__ float swf[432];
    __shared__ float sbf[16];
    int tid = threadIdx.x;
    if (blockIdx.x < 1024) {
        int v = blockIdx.x*256 + tid;
        int x = v>>12, y = (v>>6)&63, z = v&63;
        const int LUT[8] = {0,5,4,3,4,2,1,5};
        int par = ((x&1)<<2)|((y&1)<<1)|(z&1);
        int gid = LUT[par];
        int mid = ((x>>1)+(y>>1)+(z>>1)) % 3;
        bool O = g_pocc[((x>>1)<<10)|((y>>1)<<5)|(z>>1)] != 0;
        bool X = g_occx[v] != 0;
        bool g0 = (gid == 0);

        bool bi[8], bo[8];
        bi[0] = O && g0 && (mid==0);
        bi[1] = (O && g0 && mid==1) || (X && g0 && mid==0);
        bi[2] = (X && g0 && mid<2)  || (O && g0 && mid==2);
        bi[3] = (X && g0)      || (O && gid==1);
        bi[4] = (X && gid<=1)  || (O && gid==2);
        bi[5] = (X && gid<=2)  || (O && gid==3);
        bi[6] = (X && gid<=3)  || (O && gid==4);
        bi[7] = (X && gid<=4)  || (O && gid==5);
        bo[0] = O && g0 && mid==0;
        bo[1] = O && g0 && mid==1;
        bo[2] = O && g0 && mid==2;
        #pragma unroll
        for (int s=3;s<8;s++) bo[s] = O && (gid == s-2);

        unsigned char mb = 0, mo = 0;
        #pragma unroll
        for (int s=0;s<8;s++) {
            if (bi[s]) mb |= (1u<<s);
            if (bo[s]) mo |= (1u<<s);
        }
        int pm = (par<<15) | ((x>>1)<<10) | ((y>>1)<<5) | (z>>1);
        g_minp[pm]  = mb;
        g_moutp[pm] = mo;
        #pragma unroll
        for (int s=0;s<8;s++) out[(s<<18)+v] = 0.f;
        #pragma unroll
        for (int s=0;s<8;s++) {
            bool lab = (s<3) ? (X && g0 && mid==s) : (X && gid==(s-2));
            out[((8+s)<<18)+v] = lab ? 1.f : 0.f;
        }
    } else {
        for (int i=tid;i<432;i+=256) swf[i]=wf1[i];
        if (tid<16) sbf[tid]=bf1[tid];
        __syncthreads();
        int p = (blockIdx.x-1024)*256 + tid;
        if (!g_pocc[p]) return;
        int px=p>>10, py=(p>>5)&31, pz=p&31;
        float acc[16];
        #pragma unroll
        for (int c=0;c<16;c++) acc[c]=sbf[c];
        for (int dx=-1;dx<=1;dx++){ int nx=px+dx; if ((unsigned)nx>=32u) continue;
        for (int dy=-1;dy<=1;dy++){ int ny=py+dy; if ((unsigned)ny>=32u) continue;
        for (int dz=-1;dz<=1;dz++){ int nz=pz+dz; if ((unsigned)nz>=32u) continue;
            if (!g_pocc[(nx<<10)|(ny<<5)|nz]) continue;
            int d = ((dx+1)*3+(dy+1))*3+(dz+1);
            const float* wr = swf + d*16;
            #pragma unroll
            for (int c=0;c<16;c++) acc[c] += wr[c];
        }}}
        float* o = g_h1 + p*16;
        #pragma unroll
        for (int c=0;c<16;c++) o[c] = fmaxf(acc[c],0.f);
    }
}

// ---------------- fused FEL conv2 + upsample -> par-major prob ----------------
__global__ void k_fel2up(const float* __restrict__ w, const float* __restrict__ b,
                         const float* __restrict__ wup, const float* __restrict__ bup) {
    __shared__ float sw[27*256];
    __shared__ float su[8*256];
    __shared__ float sb2[16];
    __shared__ float sbu[16];
    int tid = threadIdx.x;
    for (int i=tid;i<6912;i+=256) sw[i]=w[i];
    for (int i=tid;i<2048;i+=256) su[i]=wup[i];
    if (tid<16) { sb2[tid]=b[tid]; sbu[tid]=bup[tid]; }
    __syncthreads();
    int p = blockIdx.x*256 + tid;
    if (!g_pocc[p]) return;
    unsigned long long A[8];
    #pragma unroll
    for (int j=0;j<8;j++) A[j] = pk2(sb2[2*j], sb2[2*j+1]);
    int px=p>>10, py=(p>>5)&31, pz=p&31;
    for (int dx=-1;dx<=1;dx++){ int nx=px+dx; if ((unsigned)nx>=32u) continue;
    for (int dy=-1;dy<=1;dy++){ int ny=py+dy; if ((unsigned)ny>=32u) continue;
    for (int dz=-1;dz<=1;dz++){ int nz=pz+dz; if ((unsigned)nz>=32u) continue;
        int nv = (nx<<10)|(ny<<5)|nz;
        if (!g_pocc[nv]) continue;
        int d = ((dx+1)*3+(dy+1))*3+(dz+1);
        const float4* hp4 = (const float4*)(g_h1 + nv*16);
        float4 h0=hp4[0], h1=hp4[1], h2=hp4[2], h3=hp4[3];
        float in[16] = {h0.x,h0.y,h0.z,h0.w, h1.x,h1.y,h1.z,h1.w,
                        h2.x,h2.y,h2.z,h2.w, h3.x,h3.y,h3.z,h3.w};
        gemv16_f2(A, in, sw + d*256);
    }}}
    float hv[16];
    #pragma unroll
    for (int j=0;j<8;j++) upk2(A[j], hv[2*j], hv[2*j+1]);
    #pragma unroll
    for (int o=0;o<8;o++) {
        unsigned long long C[8];
        #pragma unroll
        for (int j=0;j<8;j++) C[j] = pk2(sbu[2*j], sbu[2*j+1]);
        gemv16_f2(C, hv, su + o*256);
        float* pv = g_prob + ((o<<15)|p)*16;
        #pragma unroll
        for (int j=0;j<8;j++) upk2(C[j], pv[2*j], pv[2*j+1]);
    }
}

// ---------------- conv1: dense par-major, 4 voxels/thread, f32x2 accumulators ----------------
__global__ void __launch_bounds__(256) k_conv1_all(K1 P, float* __restrict__ out) {
    int e = blockIdx.x >> 5, ch = blockIdx.x & 31;
    int s = P.es[e];
    int par = P.par[e];
    __shared__ float sw[6944];
    int tid = threadIdx.x;
    int ox = (par>>2)&1, oy = (par>>1)&1, oz = par&1;

    if (s == 0) {
        if (tid < 256) sw[tid] = P.w[0][13*256 + tid];
        if (tid < 16)  sw[6912+tid] = P.w20[13*16 + tid];
        if (tid < 16)  sw[6928+tid] = P.b[0][tid];
        __syncthreads();
        #pragma unroll
        for (int h=0; h<4; h++) {
            int pi = ch*1024 + h*256 + tid;
            if (!(g_minp[pi] & 1)) continue;
            const float4* pin = (const float4*)(g_prob + pi*16);
            float4 i0=pin[0], i1=pin[1], i2=pin[2], i3=pin[3];
            float in[16] = {i0.x,i0.y,i0.z,i0.w, i1.x,i1.y,i1.z,i1.w,
                            i2.x,i2.y,i2.z,i2.w, i3.x,i3.y,i3.z,i3.w};
            float a[16];
            #pragma unroll
            for (int c=0;c<16;c++) a[c]=sw[6928+c];
            #pragma unroll
            for (int cin=0;cin<16;cin++){
                float vv = in[cin];
                #pragma unroll
                for (int c=0;c<16;c++) a[c] += vv*sw[cin*16+c];
            }
            float acc = P.b20[0];
            #pragma unroll
            for (int c=0;c<16;c++) acc += fmaxf(a[c],0.f)*sw[6912+c];
            int xv = ((pi>>10)<<1), yv = (((pi>>5)&31)<<1), zv = ((pi&31)<<1);
            out[(xv<<12)|(yv<<6)|zv] = 1.f/(1.f + expf(-acc));
        }
        return;
    }

    bool is5 = (s==1 || s==2);
    const float* w = P.w[s];
    if (is5) {
        for (int i=tid;i<6912;i+=256) {
            int t=i>>8, c=i&255;
            int a=t/9, bb=(t/3)%3, cc=t%3;
            sw[i] = w[(((2*a)*5+2*bb)*5+2*cc)*256 + c];
        }
    } else {
        for (int i=tid;i<6912;i+=256) sw[i]=w[i];
    }
    __syncthreads();
    int pi0 = ch*1024 + tid;
    int xa = ((pi0>>10)<<1)|ox, ya = (((pi0>>5)&31)<<1)|oy, za = ((pi0&31)<<1)|oz;
    int sc = is5 ? 2 : 1;
    unsigned m = P.cand[e];
    const float* bbx = P.b[s];
    unsigned long long A0[8], A1[8], A2[8], A3[8];
    #pragma unroll
    for (int j=0;j<8;j++) {
        unsigned long long b2 = pk2(bbx[2*j], bbx[2*j+1]);
        A0[j]=b2; A1[j]=b2; A2[j]=b2; A3[j]=b2;
    }
    while (m) {
        int t = __ffs(m)-1; m &= m-1;
        int dx = sc*(t/9-1), dy = sc*((t/3)%3-1), dz = sc*(t%3-1);
        int nx=xa+dx, nz=za+dz;
        int ny0=ya+dy, ny1=ny0+16, ny2=ny0+32, ny3=ny0+48;
        int mx=nx&63, mz=nz&63;
        bool ib0 = ((unsigned)(nx|ny0|nz) < 64u);
        bool ib1 = ((unsigned)(nx|ny1|nz) < 64u);
        bool ib2 = ((unsigned)(nx|ny2|nz) < 64u);
        bool ib3 = ((unsigned)(nx|ny3|nz) < 64u);
        int npp  = ((((mx&1)<<2)|((ny0&1)<<1)|(mz&1))<<15) | ((mx>>1)<<10) | (mz>>1);
        int np0 = npp | (((ny0&63)>>1)<<5);
        int np1 = npp | (((ny1&63)>>1)<<5);
        int np2 = npp | (((ny2&63)>>1)<<5);
        int np3 = npp | (((ny3&63)>>1)<<5);
        float s0 = (ib0 && ((g_minp[np0]>>s)&1)) ? 1.f : 0.f;
        float s1 = (ib1 && ((g_minp[np1]>>s)&1)) ? 1.f : 0.f;
        float s2 = (ib2 && ((g_minp[np2]>>s)&1)) ? 1.f : 0.f;
        float s3 = (ib3 && ((g_minp[np3]>>s)&1)) ? 1.f : 0.f;
        const float4* p0 = (const float4*)(g_prob + np0*16);
        const float4* p1 = (const float4*)(g_prob + np1*16);
        const float4* p2 = (const float4*)(g_prob + np2*16);
        const float4* p3 = (const float4*)(g_prob + np3*16);
        const ulonglong2* pw2 = (const ulonglong2*)(sw + t*256);
        #pragma unroll
        for (int q4=0;q4<4;q4++){
            float4 u0 = p0[q4], u1 = p1[q4], u2 = p2[q4], u3 = p3[q4];
            u0.x*=s0; u0.y*=s0; u0.z*=s0; u0.w*=s0;
            u1.x*=s1; u1.y*=s1; u1.z*=s1; u1.w*=s1;
            u2.x*=s2; u2.y*=s2; u2.z*=s2; u2.w*=s2;
            u3.x*=s3; u3.y*=s3; u3.z*=s3; u3.w*=s3;
            #pragma unroll
            for (int k=0;k<4;k++){
                int cin = q4*4 + k;
                unsigned long long a2 = pk2((&u0.x)[k]);
                unsigned long long b2 = pk2((&u1.x)[k]);
                unsigned long long c2 = pk2((&u2.x)[k]);
                unsigned long long d2 = pk2((&u3.x)[k]);
                ulonglong2 w01 = pw2[cin*4+0];
                ulonglong2 w23 = pw2[cin*4+1];
                ulonglong2 w45 = pw2[cin*4+2];
                ulonglong2 w67 = pw2[cin*4+3];
                f2fma(A0[0],a2,w01.x); f2fma(A0[1],a2,w01.y);
                f2fma(A0[2],a2,w23.x); f2fma(A0[3],a2,w23.y);
                f2fma(A0[4],a2,w45.x); f2fma(A0[5],a2,w45.y);
                f2fma(A0[6],a2,w67.x); f2fma(A0[7],a2,w67.y);
                f2fma(A1[0],b2,w01.x); f2fma(A1[1],b2,w01.y);
                f2fma(A1[2],b2,w23.x); f2fma(A1[3],b2,w23.y);
                f2fma(A1[4],b2,w45.x); f2fma(A1[5],b2,w45.y);
                f2fma(A1[6],b2,w67.x); f2fma(A1[7],b2,w67.y);
                f2fma(A2[0],c2,w01.x); f2fma(A2[1],c2,w01.y);
                f2fma(A2[2],c2,w23.x); f2fma(A2[3],c2,w23.y);
                f2fma(A2[4],c2,w45.x); f2fma(A2[5],c2,w45.y);
                f2fma(A2[6],c2,w67.x); f2fma(A2[7],c2,w67.y);
                f2fma(A3[0],d2,w01.x); f2fma(A3[1],d2,w01.y);
                f2fma(A3[2],d2,w23.x); f2fma(A3[3],d2,w23.y);
                f2fma(A3[4],d2,w45.x); f2fma(A3[5],d2,w45.y);
                f2fma(A3[6],d2,w67.x); f2fma(A3[7],d2,w67.y);
            }
        }
    }
    float* hb = g_hs[s];
    {
        float r[16];
        #pragma unroll
        for (int j=0;j<8;j++) upk2(A0[j], r[2*j], r[2*j+1]);
        float4* ph = (float4*)(hb + ((par<<15)|pi0)*16);
        ph[0]=make_float4(fmaxf(r[0],0.f),fmaxf(r[1],0.f),fmaxf(r[2],0.f),fmaxf(r[3],0.f));
        ph[1]=make_float4(fmaxf(r[4],0.f),fmaxf(r[5],0.f),fmaxf(r[6],0.f),fmaxf(r[7],0.f));
        ph[2]=make_float4(fmaxf(r[8],0.f),fmaxf(r[9],0.f),fmaxf(r[10],0.f),fmaxf(r[11],0.f));
        ph[3]=make_float4(fmaxf(r[12],0.f),fmaxf(r[13],0.f),fmaxf(r[14],0.f),fmaxf(r[15],0.f));
    }
    {
        float r[16];
        #pragma unroll
        for (int j=0;j<8;j++) upk2(A1[j], r[2*j], r[2*j+1]);
        float4* ph = (float4*)(hb + ((par<<15)|(pi0+256))*16);
        ph[0]=make_float4(fmaxf(r[0],0.f),fmaxf(r[1],0.f),fmaxf(r[2],0.f),fmaxf(r[3],0.f));
        ph[1]=make_float4(fmaxf(r[4],0.f),fmaxf(r[5],0.f),fmaxf(r[6],0.f),fmaxf(r[7],0.f));
        ph[2]=make_float4(fmaxf(r[8],0.f),fmaxf(r[9],0.f),fmaxf(r[10],0.f),fmaxf(r[11],0.f));
        ph[3]=make_float4(fmaxf(r[12],0.f),fmaxf(r[13],0.f),fmaxf(r[14],0.f),fmaxf(r[15],0.f));
    }
    {
        float r[16];
        #pragma unroll
        for (int j=0;j<8;j++) upk2(A2[j], r[2*j], r[2*j+1]);
        float4* ph = (float4*)(hb + ((par<<15)|(pi0+512))*16);
        ph[0]=make_float4(fmaxf(r[0],0.f),fmaxf(r[1],0.f),fmaxf(r[2],0.f),fmaxf(r[3],0.f));
        ph[1]=make_float4(fmaxf(r[4],0.f),fmaxf(r[5],0.f),fmaxf(r[6],0.f),fmaxf(r[7],0.f));
        ph[2]=make_float4(fmaxf(r[8],0.f),fmaxf(r[9],0.f),fmaxf(r[10],0.f),fmaxf(r[11],0.f));
        ph[3]=make_float4(fmaxf(r[12],0.f),fmaxf(r[13],0.f),fmaxf(r[14],0.f),fmaxf(r[15],0.f));
    }
    {
        float r[16];
        #pragma unroll
        for (int j=0;j<8;j++) upk2(A3[j], r[2*j], r[2*j+1]);
        float4* ph = (float4*)(hb + ((par<<15)|(pi0+768))*16);
        ph[0]=make_float4(fmaxf(r[0],0.f),fmaxf(r[1],0.f),fmaxf(r[2],0.f),fmaxf(r[3],0.f));
        ph[1]=make_float4(fmaxf(r[4],0.f),fmaxf(r[5],0.f),fmaxf(r[6],0.f),fmaxf(r[7],0.f));
        ph[2]=make_float4(fmaxf(r[8],0.f),fmaxf(r[9],0.f),fmaxf(r[10],0.f),fmaxf(r[11],0.f));
        ph[3]=make_float4(fmaxf(r[12],0.f),fmaxf(r[13],0.f),fmaxf(r[14],0.f),fmaxf(r[15],0.f));
    }
}

// ---------------- conv2: dense par-major ----------------
__global__ void __launch_bounds__(256) k_conv2_all(K2 P, float* __restrict__ out) {
    int e = blockIdx.x >> 7, ch = blockIdx.x & 127;
    int s = P.es[e];
    int par = P.par[e];
    __shared__ float sw[432];
    int tid = threadIdx.x;
    bool is5 = (s==1 || s==2);
    const float* w = P.w[s];
    if (is5) {
        for (int i=tid;i<432;i+=256) {
            int t=i>>4, c=i&15;
            int a=t/9, bb=(t/3)%3, cc=t%3;
            sw[i] = w[(((2*a)*5+2*bb)*5+2*cc)*16 + c];
        }
    } else {
        for (int i=tid;i<432;i+=256) sw[i]=w[i];
    }
    __syncthreads();
    int pi = ch*256 + tid;
    int pm = (par<<15)|pi;
    if (!((g_moutp[pm]>>s)&1)) return;
    int ox = (par>>2)&1, oy = (par>>1)&1, oz = par&1;
    int x = ((pi>>10)<<1)|ox, y = (((pi>>5)&31)<<1)|oy, z = ((pi&31)<<1)|oz;
    int sc = is5 ? 2 : 1;
    unsigned m = P.cand[e];
    const float* hbase = g_hs[s];
    float acc = P.b[s][0];
    while (m) {
        int t = __ffs(m)-1; m &= m-1;
        int nx = x + sc*(t/9-1), ny = y + sc*((t/3)%3-1), nz = z + sc*(t%3-1);
        bool inb = ((unsigned)(nx|ny|nz) < 64u);
        int mx=nx&63, my=ny&63, mz=nz&63;
        int npm = ((((mx&1)<<2)|((my&1)<<1)|(mz&1))<<15) | ((mx>>1)<<10)|((my>>1)<<5)|(mz>>1);
        float sel = (inb && ((g_minp[npm]>>s)&1)) ? 1.f : 0.f;
        const float4* pc = (const float4*)(hbase + npm*16);
        float4 c0=pc[0], c1=pc[1], c2=pc[2], c3=pc[3];
        const float* wr = sw + t*16;
        float d = c0.x*wr[0] + c0.y*wr[1] + c0.z*wr[2] + c0.w*wr[3]
                + c1.x*wr[4] + c1.y*wr[5] + c1.z*wr[6] + c1.w*wr[7]
                + c2.x*wr[8] + c2.y*wr[9] + c2.z*wr[10]+ c2.w*wr[11]
                + c3.x*wr[12]+ c3.y*wr[13]+ c3.z*wr[14]+ c3.w*wr[15];
        acc += sel*d;
    }
    out[(s<<18) | (x<<12)|(y<<6)|z] = 1.f/(1.f + expf(-acc));
}

// ---------------- host-side construction ----------------
static const int GIDH[8] = {0,5,4,3,4,2,1,5};

static unsigned mask3(int s, int par) {
    unsigned m=0;
    for (int t=0;t<27;t++) {
        int dx=t/9-1, dy=(t/3)%3-1, dz=t%3-1;
        int pn = par ^ ((((dx&1))<<2)|(((dy&1))<<1)|(dz&1));
        if (GIDH[pn] <= s-2) m |= 1u<<t;
    }
    return m;
}

// ---------------- launch ----------------
extern "C" void kernel_launch(void* const* d_in, const int* in_sizes, int n_in,
                              void* d_out, int out_size) {
    const float* x      = (const float*)d_in[0];
    const float* w_fel1 = (const float*)d_in[3];
    const float* b_fel1 = (const float*)d_in[4];
    const float* w_fel2 = (const float*)d_in[5];
    const float* b_fel2 = (const float*)d_in[6];
    const float* w_up   = (const float*)d_in[7];
    const float* b_up   = (const float*)d_in[8];
    const float* wc1    = (const float*)d_in[9];
    const float* bc1    = (const float*)d_in[10];
    const float* wc2    = (const float*)d_in[11];
    const float* bc2    = (const float*)d_in[12];
    const float* wl1    = (const float*)d_in[13];
    const float* bl1    = (const float*)d_in[14];
    const float* wl2    = (const float*)d_in[15];
    const float* bl2    = (const float*)d_in[16];
    float* out = (float*)d_out;

    K1 p1; K2 p2;
    for (int s=0;s<8;s++) {
        if (s==1 || s==2) {
            p1.w[s] = wl1 + (s-1)*125*256; p1.b[s] = bl1 + (s-1)*16;
            p2.w[s] = wl2 + (s-1)*125*16;  p2.b[s] = bl2 + (s-1);
        } else {
            int k = (s==0) ? 0 : (s-2);
            p1.w[s] = wc1 + k*27*256; p1.b[s] = bc1 + k*16;
            p2.w[s] = wc2 + k*27*16;  p2.b[s] = bc2 + k;
        }
    }
    p1.w20 = wc2; p1.b20 = bc2;

    int n1 = 0;
    for (int s=0;s<8;s++)
        for (int par=0;par<8;par++) {
            bool incl = (s<=2) ? (par==0) : (GIDH[par] <= s-2);
            if (!incl) continue;
            p1.es[n1]  = (unsigned char)s;
            p1.par[n1] = (unsigned char)par;
            p1.cand[n1] = (s==0) ? (1u<<13)
                        : (s<=2) ? 0x07FFFFFFu
                                 : mask3(s,par);
            n1++;
        }
    p1.n_ent = n1;

    int n2 = 0;
    for (int s=1;s<8;s++)
        for (int par=0;par<8;par++) {
            bool incl = (s<=2) ? (par==0) : (GIDH[par] == s-2);
            if (!incl) continue;
            p2.es[n2]  = (unsigned char)s;
            p2.par[n2] = (unsigned char)par;
            p2.cand[n2] = (s<=2) ? 0x07FFFFFFu : mask3(s,par);
            n2++;
        }
    p2.n_ent = n2;

    k_init<<<128,256>>>(x);
    k_maskfel1<<<1152,256>>>(out, w_fel1, b_fel1);
    k_fel2up<<<128,256>>>(w_fel2, b_fel2, w_up, b_up);
    k_conv1_all<<<n1*32,256>>>(p1, out);
    k_conv2_all<<<n2*128,256>>>(p2, out);
}